// round 4
// baseline (speedup 1.0000x reference)
#include <cuda_runtime.h>

#define KNEI 8
#define EHID 16
#define BLK  128   // agents per block == threads per block

__device__ __forceinline__ float ex2f(float x) {
    float r; asm("ex2.approx.f32 %0, %1;" : "=f"(r) : "f"(x)); return r;
}
__device__ __forceinline__ unsigned smem_u32(const void* p) {
    return (unsigned)__cvta_generic_to_shared(p);
}
__device__ __forceinline__ void cpa16(unsigned dst, const void* src) {
    asm volatile("cp.async.ca.shared.global [%0], [%1], 16;" :: "r"(dst), "l"(src) : "memory");
}

struct Net { float w[EHID]; float c[EHID]; float bias; int nnz; };
__device__ Net  g_nets[4];   // 0=rep, 1=att, 2=bor, 3=del
__device__ float g_scal[8];  // inv_p0, p1, ang^2, border[0], border[3]

// ---------------------------------------------------------------------------
// Fold each mono net  y = b2 + sum_i w2_i * exp(-(w1_i x + b1_i))
// into               y = bias + sum_{w1_i != 0} c_i * exp2(w'_i * x)
// ---------------------------------------------------------------------------
__global__ void sfm_preprocess(
    const float* __restrict__ rep_w1, const float* __restrict__ rep_b1,
    const float* __restrict__ rep_w2, const float* __restrict__ rep_b2,
    const float* __restrict__ att_w1, const float* __restrict__ att_b1,
    const float* __restrict__ att_w2, const float* __restrict__ att_b2,
    const float* __restrict__ bor_w1, const float* __restrict__ bor_b1,
    const float* __restrict__ bor_w2, const float* __restrict__ bor_b2,
    const float* __restrict__ del_w1, const float* __restrict__ del_b1,
    const float* __restrict__ del_w2, const float* __restrict__ del_b2,
    const float* __restrict__ p_dest, const float* __restrict__ angle,
    const float* __restrict__ border)
{
    int t = threadIdx.x;
    if (t < 4) {
        const float* w1 = (t==0)?rep_w1:(t==1)?att_w1:(t==2)?bor_w1:del_w1;
        const float* b1 = (t==0)?rep_b1:(t==1)?att_b1:(t==2)?bor_b1:del_b1;
        const float* w2 = (t==0)?rep_w2:(t==1)?att_w2:(t==2)?bor_w2:del_w2;
        const float* b2 = (t==0)?rep_b2:(t==1)?att_b2:(t==2)?bor_b2:del_b2;
        const float LOG2E = 1.4426950408889634f;
        float bias = b2[0];
        int m = 0;
        for (int i = 0; i < EHID; i++) {
            float ci = w2[i] * expf(-b1[i]);
            float wi = w1[i];
            if (wi != 0.0f) {
                g_nets[t].w[m] = -wi * LOG2E;
                g_nets[t].c[m] = ci;
                m++;
            } else {
                bias += ci;
            }
        }
        for (int i = m; i < EHID; i++) { g_nets[t].w[i] = 0.0f; g_nets[t].c[i] = 0.0f; }
        g_nets[t].bias = bias;
        g_nets[t].nnz  = m;
    } else if (t == 4) {
        g_scal[0] = 1.0f / p_dest[0];
        g_scal[1] = p_dest[1];
        float a = angle[0];
        g_scal[2] = a * a;
        g_scal[3] = border[0];
        g_scal[4] = border[3];
    }
}

template <int NB>
__device__ __forceinline__ void mono_batch(const float2* __restrict__ terms,
                                           int nn, float bias,
                                           const float* __restrict__ x,
                                           float* __restrict__ y)
{
#pragma unroll
    for (int k = 0; k < NB; k++) y[k] = bias;
    for (int t = 0; t < nn; t++) {
        float2 wc = terms[t];
#pragma unroll
        for (int k = 0; k < NB; k++)
            y[k] = fmaf(wc.y, ex2f(wc.x * x[k]), y[k]);
    }
}

__device__ __forceinline__ float mono1(const float2* __restrict__ terms,
                                       int nn, float bias, float x)
{
    float y = bias;
    for (int t = 0; t < nn; t++) {
        float2 wc = terms[t];
        y = fmaf(wc.y, ex2f(wc.x * x), y);
    }
    return y;
}

__global__ void __launch_bounds__(BLK)
sfm_main(const float* __restrict__ ego, const float* __restrict__ nei,
         const float* __restrict__ rec, float* __restrict__ out, int N)
{
    // Padded stage: rows of 129 float4 (pad kills STS bank conflicts;
    // reads are lane==column -> conflict-free).
    __shared__ float4 sNei[16 * 129];   // [rh = r*2+h][agent]   33,024 B
    __shared__ float4 sEgo[4  * 129];   // [q][agent]             8,256 B
    __shared__ float2 sT[4][EHID];
    __shared__ float  sB[4];
    __shared__ int    sN[4];
    __shared__ float  sS[8];

    int t = threadIdx.x;
    int base = blockIdx.x * BLK;

    if (t < 64) {
        int q = t >> 4, i = t & 15;
        sT[q][i] = make_float2(g_nets[q].w[i], g_nets[q].c[i]);
    } else if (t < 68) {
        sB[t - 64] = g_nets[t - 64].bias;
        sN[t - 64] = g_nets[t - 64].nnz;
    } else if (t < 73) {
        sS[t - 68] = g_scal[t - 68];
    }

    // ---- coalesced staging of nei (first 32B of each 64B row) ----
    // j in [0, 2048): a = j/16, rh = j%16 (r = rh/2, h = rh%2)
    // gmem offset = a*512 + r*64 + h*16 ; warp-wide LDGSTS spans 8 lines.
#pragma unroll
    for (int i = 0; i < 16; i++) {
        int j  = i * BLK + t;
        int a  = j >> 4;
        int rh = j & 15;
        int r  = rh >> 1, h = rh & 1;
        int ac = min(base + a, N - 1);
        const char* src = (const char*)nei + (size_t)ac * 512 + r * 64 + h * 16;
        cpa16(smem_u32(&sNei[rh * 129 + a]), src);
    }
    // ---- coalesced staging of ego (full 64B rows) ----
    // j in [0, 512): a = j/4, q = j%4
#pragma unroll
    for (int i = 0; i < 4; i++) {
        int j = i * BLK + t;
        int a = j >> 2;
        int q = j & 3;
        int ac = min(base + a, N - 1);
        const char* src = (const char*)ego + (size_t)ac * 64 + q * 16;
        cpa16(smem_u32(&sEgo[q * 129 + a]), src);
    }
    asm volatile("cp.async.commit_group;" ::: "memory");

    // ---- rec: direct per-thread loads, in flight during the wait ----
    int n = base + t;
    int nc = min(n, N - 1);
    const float4* r4 = reinterpret_cast<const float4*>(rec) + (size_t)nc * 4;
    float4 rA = r4[0], rB = r4[1], rC = r4[2], rD = r4[3];

    asm volatile("cp.async.wait_group 0;" ::: "memory");
    __syncthreads();

    // ================= per-agent compute, all operands from smem ===========
    float4 e0 = sEgo[0 * 129 + t];
    float4 e1 = sEgo[1 * 129 + t];
    float4 e2 = sEgo[2 * 129 + t];
    float4 e3 = sEgo[3 * 129 + t];
    float px = e0.y, py = e0.z;
    float vx = e0.w, vy = e1.x;
    float ids[8] = { e1.w, e2.x, e2.y, e2.z, e2.w, e3.x, e3.y, e3.z };

    float nid[8], rnv[8], bv[8], dx[8], dy[8];
    bool  idxk[8];
#pragma unroll
    for (int k = 0; k < 8; k++) {
        float4 a  = sNei[(k * 2) * 129 + t];        // id, px, py, vnx
        float  vny = sNei[(k * 2 + 1) * 129 + t].x; // vny
        nid[k] = a.x;

        bool m = false;
#pragma unroll
        for (int j = 0; j < 8; j++) m |= (a.x == ids[j]);
        bool ix = m && (a.x != 0.0f);
        idxk[k] = ix;

        float rx = a.y - px, ry = a.z - py;
        float s  = rx * rx + ry * ry;
        float ir = rsqrtf(s);
        float rn = s * ir;
        rnv[k] = rn;
        dx[k]  = rx * ir;
        dy[k]  = ry * ir;

        float vdx = a.w * 0.02f, vdy = vny * 0.02f;
        float tx = rx + vdx, ty = ry + vdy;
        float bb = rn + tx * tx + ty * ty - (vdx * vdx + vdy * vdy);
        bb = ix ? bb : 1.0f;
        bv[k] = __fsqrt_rn(fmaxf(bb, 1e-12f)) * 0.5f;
    }

    // ---- att / rep nets ----
    float att8[8], rep8[8];
    mono_batch<8>(sT[1], sN[1], sB[1], rnv, att8);
    mono_batch<8>(sT[0], sN[0], sB[0], bv,  rep8);

    // ---- buffer / count logic ----
    float bid[8] = { rA.x, rA.z, rB.x, rB.z, rC.x, rC.z, rD.x, rD.z };
    float bct[8] = { rA.y, rA.w, rB.y, rB.w, rC.y, rC.w, rD.y, rD.w };

    bool  ifin[8];
    float ct2[8];
#pragma unroll
    for (int k = 0; k < 8; k++) {
        bool f = false;
#pragma unroll
        for (int j = 0; j < 8; j++) f |= (bid[k] == nid[j]);
        ifin[k] = f;
        ct2[k]  = bct[k] + (f ? 1.0f : 0.0f);
    }

    float count[8];
#pragma unroll
    for (int i = 0; i < 8; i++) {
        float ci = 1.0f;
        int seen = 0;
#pragma unroll
        for (int k = 0; k < 8; k++) {
            bool take = ifin[k] && (seen == i);
            ci = take ? ct2[k] : ci;
            seen += ifin[k] ? 1 : 0;
        }
        count[i] = ci;
    }

    // ---- del net (warp-uniform fast path) ----
    bool same = true;
#pragma unroll
    for (int i = 1; i < 8; i++) same &= (count[i] == count[0]);
    float del8[8];
    if (__all_sync(0xffffffffu, same)) {
        float du = mono1(sT[3], sN[3], sB[3], count[0]);
#pragma unroll
        for (int k = 0; k < 8; k++) del8[k] = du;
    } else {
        mono_batch<8>(sT[3], sN[3], sB[3], count, del8);
    }

    float v2   = vx * vx + vy * vy;
    float ang2 = sS[2];

    // ---- neighbor forces, angle-clamped (squared form) ----
    float fnx = 0.0f, fny = 0.0f;
#pragma unroll
    for (int k = 0; k < 8; k++) {
        bool ix = idxk[k];
        float da  = del8[k] * att8[k];
        float fax = ix ? da * dx[k] : 0.0f;
        float fay = ix ? da * dy[k] : 0.0f;
        float frx = ix ? rep8[k] * dx[k] : 0.0f;
        float fry = ix ? rep8[k] * dy[k] : 0.0f;

        float num = vx * fax + vy * fay;
        float nn  = fax * fax + fay * fay;
        bool keep = num * num > ang2 * fmaxf(v2 * nn, 1e-16f);
        fnx += keep ? fax : 0.0f;
        fny += keep ? fay : 0.0f;

        num  = vx * frx + vy * fry;
        nn   = frx * frx + fry * fry;
        keep = num * num > ang2 * fmaxf(v2 * nn, 1e-16f);
        fnx += keep ? frx : 0.0f;
        fny += keep ? fry : 0.0f;
    }

    // ---- destination force ----
    float speed = __fsqrt_rn(v2);
    float ip0 = sS[0], p1 = sS[1];
    float fdx = (p1 * speed - vx) * ip0;
    float fdy = (-vy) * ip0;
    {
        float num = vx * fdx + vy * fdy;
        float nn  = fdx * fdx + fdy * fdy;
        bool keep = num * num > ang2 * fmaxf(v2 * nn, 1e-16f);
        fdx = keep ? fdx : 0.0f;
        fdy = keep ? fdy : 0.0f;
    }

    // ---- border force (y only) ----
    float bxc = e0.z;
    float rb0 = bxc - sS[3];
    float rb1 = bxc - sS[4];
    float rbn[2] = { fabsf(rb0), fabsf(rb1) };
    float bmag[2];
    mono_batch<2>(sT[2], sN[2], sB[2], rbn, bmag);
    float fby = 0.0f;
    {
        float fv = bmag[0] * copysignf(1.0f, rb0);
        float num = vy * fv, nn = fv * fv;
        if (num * num > ang2 * fmaxf(v2 * nn, 1e-16f)) fby += fv;
        fv = bmag[1] * copysignf(1.0f, rb1);
        num = vy * fv; nn = fv * fv;
        if (num * num > ang2 * fmaxf(v2 * nn, 1e-16f)) fby += fv;
    }

    // ---- output: (N, 3, 2) ----
    if (n < N) {
        float2* o = reinterpret_cast<float2*>(out) + (size_t)n * 3;
        o[0] = make_float2(fdx, fdy);
        o[1] = make_float2(fnx, fny);
        o[2] = make_float2(0.0f, fby);
    }
}

extern "C" void kernel_launch(void* const* d_in, const int* in_sizes, int n_in,
                              void* d_out, int out_size)
{
    const float* ego    = (const float*)d_in[0];
    const float* nei    = (const float*)d_in[1];
    const float* border = (const float*)d_in[2];
    const float* rec    = (const float*)d_in[3];
    const float* p_dest = (const float*)d_in[4];
    const float* angle  = (const float*)d_in[5];

    sfm_preprocess<<<1, 32>>>(
        (const float*)d_in[6],  (const float*)d_in[7],  (const float*)d_in[8],  (const float*)d_in[9],
        (const float*)d_in[10], (const float*)d_in[11], (const float*)d_in[12], (const float*)d_in[13],
        (const float*)d_in[14], (const float*)d_in[15], (const float*)d_in[16], (const float*)d_in[17],
        (const float*)d_in[18], (const float*)d_in[19], (const float*)d_in[20], (const float*)d_in[21],
        p_dest, angle, border);

    int N = in_sizes[0] / 16;
    int blocks = (N + BLK - 1) / BLK;
    sfm_main<<<blocks, BLK>>>(ego, nei, rec, (float*)d_out, N);
}

// round 5
// speedup vs baseline: 1.3879x; 1.3879x over previous
#include <cuda_runtime.h>

#define KNEI 8
#define EHID 16
// 256 threads per block = 128 agents per block, 2 threads per agent.

__device__ __forceinline__ float ex2f(float x) {
    float r; asm("ex2.approx.f32 %0, %1;" : "=f"(r) : "f"(x)); return r;
}

struct Net { float w[EHID]; float c[EHID]; float bias; int nnz; };
__device__ Net  g_nets[4];   // 0=rep, 1=att, 2=bor, 3=del
__device__ float g_scal[8];  // inv_p0, p1, ang^2, border[0], border[3]

// ---------------------------------------------------------------------------
// Fold each mono net  y = b2 + sum_i w2_i * exp(-(w1_i x + b1_i))
// into               y = bias + sum_{w1_i != 0} c_i * exp2(w'_i * x)
// ---------------------------------------------------------------------------
__global__ void sfm_preprocess(
    const float* __restrict__ rep_w1, const float* __restrict__ rep_b1,
    const float* __restrict__ rep_w2, const float* __restrict__ rep_b2,
    const float* __restrict__ att_w1, const float* __restrict__ att_b1,
    const float* __restrict__ att_w2, const float* __restrict__ att_b2,
    const float* __restrict__ bor_w1, const float* __restrict__ bor_b1,
    const float* __restrict__ bor_w2, const float* __restrict__ bor_b2,
    const float* __restrict__ del_w1, const float* __restrict__ del_b1,
    const float* __restrict__ del_w2, const float* __restrict__ del_b2,
    const float* __restrict__ p_dest, const float* __restrict__ angle,
    const float* __restrict__ border)
{
    int t = threadIdx.x;
    if (t < 4) {
        const float* w1 = (t==0)?rep_w1:(t==1)?att_w1:(t==2)?bor_w1:del_w1;
        const float* b1 = (t==0)?rep_b1:(t==1)?att_b1:(t==2)?bor_b1:del_b1;
        const float* w2 = (t==0)?rep_w2:(t==1)?att_w2:(t==2)?bor_w2:del_w2;
        const float* b2 = (t==0)?rep_b2:(t==1)?att_b2:(t==2)?bor_b2:del_b2;
        const float LOG2E = 1.4426950408889634f;
        float bias = b2[0];
        int m = 0;
        for (int i = 0; i < EHID; i++) {
            float ci = w2[i] * expf(-b1[i]);
            float wi = w1[i];
            if (wi != 0.0f) {
                g_nets[t].w[m] = -wi * LOG2E;
                g_nets[t].c[m] = ci;
                m++;
            } else {
                bias += ci;
            }
        }
        for (int i = m; i < EHID; i++) { g_nets[t].w[i] = 0.0f; g_nets[t].c[i] = 0.0f; }
        g_nets[t].bias = bias;
        g_nets[t].nnz  = m;
    } else if (t == 4) {
        g_scal[0] = 1.0f / p_dest[0];
        g_scal[1] = p_dest[1];
        float a = angle[0];
        g_scal[2] = a * a;
        g_scal[3] = border[0];
        g_scal[4] = border[3];
    }
}

template <int NB>
__device__ __forceinline__ void mono_batch(const float2* __restrict__ terms,
                                           int nn, float bias,
                                           const float* __restrict__ x,
                                           float* __restrict__ y)
{
#pragma unroll
    for (int k = 0; k < NB; k++) y[k] = bias;
    for (int t = 0; t < nn; t++) {
        float2 wc = terms[t];
#pragma unroll
        for (int k = 0; k < NB; k++)
            y[k] = fmaf(wc.y, ex2f(wc.x * x[k]), y[k]);
    }
}

__device__ __forceinline__ float mono1(const float2* __restrict__ terms,
                                       int nn, float bias, float x)
{
    float y = bias;
    for (int t = 0; t < nn; t++) {
        float2 wc = terms[t];
        y = fmaf(wc.y, ex2f(wc.x * x), y);
    }
    return y;
}

__global__ void __launch_bounds__(256, 4)
sfm_main(const float* __restrict__ ego, const float* __restrict__ nei,
         const float* __restrict__ rec, float* __restrict__ out, int N)
{
    __shared__ float2 sT[4][EHID];
    __shared__ float  sB[4];
    __shared__ int    sN[4];
    __shared__ float  sS[8];

    int t = threadIdx.x;
    if (t < 64) {
        int q = t >> 4, i = t & 15;
        sT[q][i] = make_float2(g_nets[q].w[i], g_nets[q].c[i]);
    } else if (t < 68) {
        sB[t - 64] = g_nets[t - 64].bias;
        sN[t - 64] = g_nets[t - 64].nnz;
    } else if (t < 73) {
        sS[t - 68] = g_scal[t - 68];
    }
    __syncthreads();

    int pid = t >> 1;          // pair (agent) index within block
    int h   = t & 1;           // half: this thread owns neighbor/buffer slots 4h..4h+3
    int n   = blockIdx.x * 128 + pid;
    if (n >= N) return;        // whole pairs exit together

    unsigned amask = __activemask();

    // ============ front-batched loads: own 4 nei rows + full ego + own rec half
    const float* nb = nei + (size_t)n * (KNEI * 16);
    float4 a4[4];
    float  vny[4];
#pragma unroll
    for (int j = 0; j < 4; j++)
        a4[j] = *reinterpret_cast<const float4*>(nb + (size_t)(4 * h + j) * 16);
#pragma unroll
    for (int j = 0; j < 4; j++)
        vny[j] = __ldg(nb + (size_t)(4 * h + j) * 16 + 4);   // same sector as a4[j]

    const float4* e4 = reinterpret_cast<const float4*>(ego) + (size_t)n * 4;
    float4 e0 = e4[0], e1 = e4[1], e2 = e4[2], e3 = e4[3];

    const float4* r4 = reinterpret_cast<const float4*>(rec) + (size_t)n * 4;
    float4 rr0 = r4[2 * h], rr1 = r4[2 * h + 1];

    // ============ unpack ego ============
    float px = e0.y, py = e0.z;
    float vx = e0.w, vy = e1.x;
    float ids[8] = { e1.w, e2.x, e2.y, e2.z, e2.w, e3.x, e3.y, e3.z };

    // ============ exchange neighbor ids -> full global-order nid8 ============
    float nidl[4] = { a4[0].x, a4[1].x, a4[2].x, a4[3].x };
    float nid8[8];
#pragma unroll
    for (int j = 0; j < 4; j++) {
        float o = __shfl_xor_sync(amask, nidl[j], 1);
        nid8[j]     = h ? o       : nidl[j];   // global slots 0..3
        nid8[4 + j] = h ? nidl[j] : o;         // global slots 4..7
    }

    // ============ buffer logic on own 4 slots ============
    float bidl[4] = { rr0.x, rr0.z, rr1.x, rr1.z };
    float bctl[4] = { rr0.y, rr0.w, rr1.y, rr1.w };
    unsigned mown = 0;
    float ct2l[4];
#pragma unroll
    for (int i = 0; i < 4; i++) {
        bool f = false;
#pragma unroll
        for (int j = 0; j < 8; j++) f |= (bidl[i] == nid8[j]);
        mown |= (f ? 1u : 0u) << (4 * h + i);
        ct2l[i] = bctl[i] + (f ? 1.0f : 0.0f);
    }
    unsigned m8 = mown | __shfl_xor_sync(amask, mown, 1);

    float ct8[8];
#pragma unroll
    for (int i = 0; i < 4; i++) {
        float o = __shfl_xor_sync(amask, ct2l[i], 1);
        ct8[i]     = h ? o       : ct2l[i];
        ct8[4 + i] = h ? ct2l[i] : o;
    }

    // count for own global slots gi = 4h+i: value of the slot with rank gi
    float countl[4];
#pragma unroll
    for (int i = 0; i < 4; i++) {
        int gi = 4 * h + i;
        float ci = 1.0f;
        int seen = 0;
#pragma unroll
        for (int k = 0; k < 8; k++) {
            bool b = (m8 >> k) & 1u;
            bool take = b && (seen == gi);
            ci = take ? ct8[k] : ci;
            seen += b ? 1 : 0;
        }
        countl[i] = ci;
    }

    // ============ geometry for own 4 neighbors ============
    bool  idxk[4];
    float rnv[4], bv[4], dxv[4], dyv[4];
#pragma unroll
    for (int j = 0; j < 4; j++) {
        float id = a4[j].x;
        bool m = false;
#pragma unroll
        for (int q = 0; q < 8; q++) m |= (id == ids[q]);
        bool ix = m && (id != 0.0f);
        idxk[j] = ix;

        float rx = a4[j].y - px, ry = a4[j].z - py;
        float s  = rx * rx + ry * ry;
        float ir = rsqrtf(s);
        float rn = s * ir;
        rnv[j] = rn;
        dxv[j] = rx * ir;
        dyv[j] = ry * ir;

        float vdx = a4[j].w * 0.02f, vdy = vny[j] * 0.02f;
        float tx = rx + vdx, ty = ry + vdy;
        float bb = rn + tx * tx + ty * ty - (vdx * vdx + vdy * vdy);
        bb = ix ? bb : 1.0f;
        bv[j] = __fsqrt_rn(fmaxf(bb, 1e-12f)) * 0.5f;
    }

    // ============ mono nets on own 4 ============
    float att4[4], rep4[4], del4[4];
    mono_batch<4>(sT[1], sN[1], sB[1], rnv, att4);
    mono_batch<4>(sT[0], sN[0], sB[0], bv,  rep4);

    bool same = (countl[0] == countl[1]) & (countl[0] == countl[2]) &
                (countl[0] == countl[3]);
    float oc0 = __shfl_xor_sync(amask, countl[0], 1);
    same = same && (countl[0] == oc0);
    if (__all_sync(amask, same)) {
        float du = mono1(sT[3], sN[3], sB[3], countl[0]);
#pragma unroll
        for (int j = 0; j < 4; j++) del4[j] = du;
    } else {
        mono_batch<4>(sT[3], sN[3], sB[3], countl, del4);
    }

    float v2   = vx * vx + vy * vy;
    float ang2 = sS[2];

    // ============ neighbor forces (own 4), angle-clamped, then pair-reduce ==
    float fnx = 0.0f, fny = 0.0f;
#pragma unroll
    for (int j = 0; j < 4; j++) {
        bool ix = idxk[j];
        float da  = del4[j] * att4[j];
        float fax = ix ? da * dxv[j] : 0.0f;
        float fay = ix ? da * dyv[j] : 0.0f;
        float frx = ix ? rep4[j] * dxv[j] : 0.0f;
        float fry = ix ? rep4[j] * dyv[j] : 0.0f;

        float num = vx * fax + vy * fay;
        float nn  = fax * fax + fay * fay;
        bool keep = num * num > ang2 * fmaxf(v2 * nn, 1e-16f);
        fnx += keep ? fax : 0.0f;
        fny += keep ? fay : 0.0f;

        num  = vx * frx + vy * fry;
        nn   = frx * frx + fry * fry;
        keep = num * num > ang2 * fmaxf(v2 * nn, 1e-16f);
        fnx += keep ? frx : 0.0f;
        fny += keep ? fry : 0.0f;
    }
    fnx += __shfl_xor_sync(amask, fnx, 1);
    fny += __shfl_xor_sync(amask, fny, 1);

    // ============ border force: this thread handles border term h ==========
    float bxc = e0.z;
    float rb  = bxc - sS[3 + h];
    float bm  = mono1(sT[2], sN[2], sB[2], fabsf(rb));
    float fv  = bm * copysignf(1.0f, rb);
    float fbyl = 0.0f;
    {
        float num = vy * fv, nn = fv * fv;
        if (num * num > ang2 * fmaxf(v2 * nn, 1e-16f)) fbyl = fv;
    }
    float fby = fbyl + __shfl_xor_sync(amask, fbyl, 1);

    // ============ destination force (computed by h==0 only path below) =====
    float speed = __fsqrt_rn(v2);
    float ip0 = sS[0], p1 = sS[1];
    float fdx = (p1 * speed - vx) * ip0;
    float fdy = (-vy) * ip0;
    {
        float num = vx * fdx + vy * fdy;
        float nn  = fdx * fdx + fdy * fdy;
        bool keep = num * num > ang2 * fmaxf(v2 * nn, 1e-16f);
        fdx = keep ? fdx : 0.0f;
        fdy = keep ? fdy : 0.0f;
    }

    // ============ output: (N, 3, 2); pair splits the 3 float2 stores =======
    float2* o = reinterpret_cast<float2*>(out) + (size_t)n * 3;
    if (h == 0) {
        o[0] = make_float2(fdx, fdy);
        o[1] = make_float2(fnx, fny);
    } else {
        o[2] = make_float2(0.0f, fby);
    }
}

extern "C" void kernel_launch(void* const* d_in, const int* in_sizes, int n_in,
                              void* d_out, int out_size)
{
    const float* ego    = (const float*)d_in[0];
    const float* nei    = (const float*)d_in[1];
    const float* border = (const float*)d_in[2];
    const float* rec    = (const float*)d_in[3];
    const float* p_dest = (const float*)d_in[4];
    const float* angle  = (const float*)d_in[5];

    sfm_preprocess<<<1, 32>>>(
        (const float*)d_in[6],  (const float*)d_in[7],  (const float*)d_in[8],  (const float*)d_in[9],
        (const float*)d_in[10], (const float*)d_in[11], (const float*)d_in[12], (const float*)d_in[13],
        (const float*)d_in[14], (const float*)d_in[15], (const float*)d_in[16], (const float*)d_in[17],
        (const float*)d_in[18], (const float*)d_in[19], (const float*)d_in[20], (const float*)d_in[21],
        p_dest, angle, border);

    int N = in_sizes[0] / 16;
    int blocks = (N + 127) / 128;   // 128 agents per block, 256 threads
    sfm_main<<<blocks, 256>>>(ego, nei, rec, (float*)d_out, N);
}